// round 1
// baseline (speedup 1.0000x reference)
#include <cuda_runtime.h>
#include <cuda_bf16.h>

#define TN 50000
#define TE 800000
#define FIN 256
#define NH 64

// -------- device scratch (static; no allocation allowed) --------
__device__ float g_XW[TN * 192];          // x @ [W1_v1 | W1_v2 | W1_v3]
__device__ float g_OUT1[3][TN * NH];      // conv1 accumulators -> relu'd H
__device__ float g_dinv1[3][TN];          // deg1 then rsqrt(deg1)
__device__ float g_dinv2[3][TN];          // deg2 then rsqrt(deg2)
__device__ float g_HW[3][TN];             // h @ W2 (scalar per node)
__device__ float g_O2[3][TN];             // conv2 accumulators

// -------- 1. init degrees to 1 (self-loop weight) --------
__global__ void k_init_deg() {
    int i = blockIdx.x * blockDim.x + threadIdx.x;
    if (i < 3 * TN) {
        ((float*)g_dinv1)[i] = 1.0f;
        ((float*)g_dinv2)[i] = 1.0f;
    }
}

// -------- 2. degree scatter: deg1 += w, deg2 += 1 per edge --------
__global__ void k_deg_scatter(const int* ei0, const int* ei1, const int* ei2,
                              const float* ew0, const float* ew1, const float* ew2) {
    int t = blockIdx.x * blockDim.x + threadIdx.x;
    if (t >= 3 * TE) return;
    int b = t / TE;
    int e = t - b * TE;
    const int* ei = (b == 0) ? ei0 : (b == 1) ? ei1 : ei2;
    const float* ew = (b == 0) ? ew0 : (b == 1) ? ew1 : ew2;
    int dst = ei[TE + e];
    atomicAdd(&g_dinv1[b][dst], ew[e]);
    atomicAdd(&g_dinv2[b][dst], 1.0f);
}

// -------- 3. deg -> rsqrt(deg) in place --------
__global__ void k_rsqrt() {
    int i = blockIdx.x * blockDim.x + threadIdx.x;
    if (i < 3 * TN) {
        ((float*)g_dinv1)[i] = rsqrtf(((float*)g_dinv1)[i]);
        ((float*)g_dinv2)[i] = rsqrtf(((float*)g_dinv2)[i]);
    }
}

// -------- 4. GEMM: g_XW[:, v*64:(v+1)*64] = x @ W1_v --------
// 64x64 output tile per block, 256 threads, 4x4 per thread, K-chunks of 16.
__global__ void k_gemm(const float* __restrict__ x,
                       const float* __restrict__ W1a,
                       const float* __restrict__ W1b,
                       const float* __restrict__ W1c) {
    const float* W = (blockIdx.y == 0) ? W1a : (blockIdx.y == 1) ? W1b : W1c;
    __shared__ float sx[16][65];  // [k][row], padded
    __shared__ float sw[16][64];  // [k][col]
    int row0 = blockIdx.x * 64;
    int tid = threadIdx.x;
    int ty = tid / 16, tx = tid % 16;
    float acc[4][4] = {};
    for (int k0 = 0; k0 < FIN; k0 += 16) {
        for (int i = tid; i < 64 * 16; i += 256) {
            int r = i / 16, kk = i % 16;
            int gr = row0 + r;
            sx[kk][r] = (gr < TN) ? x[gr * FIN + k0 + kk] : 0.f;
        }
        for (int i = tid; i < 16 * 64; i += 256) {
            int kk = i / 64, c = i % 64;
            sw[kk][c] = W[(k0 + kk) * NH + c];
        }
        __syncthreads();
#pragma unroll
        for (int kk = 0; kk < 16; kk++) {
            float xr[4], wc[4];
#pragma unroll
            for (int a = 0; a < 4; a++) xr[a] = sx[kk][ty + a * 16];
#pragma unroll
            for (int bb = 0; bb < 4; bb++) wc[bb] = sw[kk][tx + bb * 16];
#pragma unroll
            for (int a = 0; a < 4; a++)
#pragma unroll
                for (int bb = 0; bb < 4; bb++)
                    acc[a][bb] = fmaf(xr[a], wc[bb], acc[a][bb]);
        }
        __syncthreads();
    }
#pragma unroll
    for (int a = 0; a < 4; a++) {
        int gr = row0 + ty + a * 16;
        if (gr < TN) {
#pragma unroll
            for (int bb = 0; bb < 4; bb++)
                g_XW[gr * 192 + blockIdx.y * NH + tx + bb * 16] = acc[a][bb];
        }
    }
}

// -------- 5. out1 init: bias + self-loop message (atomic-free) --------
__global__ void k_init_out1(const float* b1a, const float* b1b, const float* b1c) {
    long t = (long)blockIdx.x * blockDim.x + threadIdx.x;
    if (t >= 3L * TN * NH) return;
    int b = (int)(t / (TN * NH));
    int rem = (int)(t - (long)b * TN * NH);
    int i = rem / NH;
    int j = rem - i * NH;
    const float* b1 = (b == 0) ? b1a : (b == 1) ? b1b : b1c;
    float d = g_dinv1[b][i];
    g_OUT1[b][rem] = b1[j] + g_XW[i * 192 + b * NH + j] * d * d;
}

// -------- 6. conv1 edge scatter: warp per (branch, edge) --------
__global__ void k_conv1_scatter(const int* ei0, const int* ei1, const int* ei2,
                                const float* ew0, const float* ew1, const float* ew2) {
    long wid = ((long)blockIdx.x * blockDim.x + threadIdx.x) >> 5;
    int lane = threadIdx.x & 31;
    if (wid >= 3L * TE) return;
    int b = (int)(wid / TE);
    int e = (int)(wid - (long)b * TE);
    const int* ei = (b == 0) ? ei0 : (b == 1) ? ei1 : ei2;
    const float* ew = (b == 0) ? ew0 : (b == 1) ? ew1 : ew2;
    int src = ei[e];
    int dst = ei[TE + e];
    float norm = g_dinv1[b][src] * ew[e] * g_dinv1[b][dst];
    const float* xw = &g_XW[src * 192 + b * NH];
    float* out = &g_OUT1[b][dst * NH];
    atomicAdd(&out[lane], xw[lane] * norm);
    atomicAdd(&out[lane + 32], xw[lane + 32] * norm);
}

// -------- 7. relu (in place -> H), features sum to d_out, hw = h@W2 --------
__global__ void k_relu_feat_hw(const float* W2a, const float* W2b, const float* W2c,
                               float* out) {
    int warp = threadIdx.x >> 5;
    int lane = threadIdx.x & 31;
    int i = blockIdx.x * (blockDim.x >> 5) + warp;
    if (i >= TN) return;
    float f0 = 0.f, f1 = 0.f;
#pragma unroll
    for (int b = 0; b < 3; b++) {
        const float* W2 = (b == 0) ? W2a : (b == 1) ? W2b : W2c;
        float* h = &g_OUT1[b][i * NH];
        float h0 = fmaxf(h[lane], 0.f);
        float h1 = fmaxf(h[lane + 32], 0.f);
        h[lane] = h0;
        h[lane + 32] = h1;
        f0 += h0;
        f1 += h1;
        float dot = h0 * W2[lane] + h1 * W2[lane + 32];
#pragma unroll
        for (int o = 16; o; o >>= 1) dot += __shfl_xor_sync(0xFFFFFFFFu, dot, o);
        if (lane == 0) g_HW[b][i] = dot;
    }
    out[TN + (long)i * NH + lane] = f0;
    out[TN + (long)i * NH + lane + 32] = f1;
}

// -------- 8. conv2 init: bias + self-loop --------
__global__ void k_init_o2(const float* b2a, const float* b2b, const float* b2c) {
    int t = blockIdx.x * blockDim.x + threadIdx.x;
    if (t >= 3 * TN) return;
    int b = t / TN;
    int i = t - b * TN;
    const float* b2 = (b == 0) ? b2a : (b == 1) ? b2b : b2c;
    float d = g_dinv2[b][i];
    g_O2[b][i] = b2[0] + g_HW[b][i] * d * d;
}

// -------- 9. conv2 edge scatter (1 scalar atomic per edge) --------
__global__ void k_conv2_scatter(const int* ei0, const int* ei1, const int* ei2) {
    int t = blockIdx.x * blockDim.x + threadIdx.x;
    if (t >= 3 * TE) return;
    int b = t / TE;
    int e = t - b * TE;
    const int* ei = (b == 0) ? ei0 : (b == 1) ? ei1 : ei2;
    int src = ei[e];
    int dst = ei[TE + e];
    float v = g_HW[b][src] * g_dinv2[b][src] * g_dinv2[b][dst];
    atomicAdd(&g_O2[b][dst], v);
}

// -------- 10. final sum of the three branch scalars --------
__global__ void k_final(float* out) {
    int i = blockIdx.x * blockDim.x + threadIdx.x;
    if (i < TN) out[i] = g_O2[0][i] + g_O2[1][i] + g_O2[2][i];
}

extern "C" void kernel_launch(void* const* d_in, const int* in_sizes, int n_in,
                              void* d_out, int out_size) {
    const float* x   = (const float*)d_in[0];
    const int*   ei0 = (const int*)d_in[1];
    const int*   ei1 = (const int*)d_in[2];
    const int*   ei2 = (const int*)d_in[3];
    const float* ew0 = (const float*)d_in[4];
    const float* ew1 = (const float*)d_in[5];
    const float* ew2 = (const float*)d_in[6];
    const float* W1a = (const float*)d_in[7];
    const float* b1a = (const float*)d_in[8];
    const float* W2a = (const float*)d_in[9];
    const float* b2a = (const float*)d_in[10];
    const float* W1b = (const float*)d_in[11];
    const float* b1b = (const float*)d_in[12];
    const float* W2b = (const float*)d_in[13];
    const float* b2b = (const float*)d_in[14];
    const float* W1c = (const float*)d_in[15];
    const float* b1c = (const float*)d_in[16];
    const float* W2c = (const float*)d_in[17];
    const float* b2c = (const float*)d_in[18];
    float* out = (float*)d_out;

    // 1-3: degree norms
    k_init_deg<<<(3 * TN + 255) / 256, 256>>>();
    k_deg_scatter<<<(3 * TE + 255) / 256, 256>>>(ei0, ei1, ei2, ew0, ew1, ew2);
    k_rsqrt<<<(3 * TN + 255) / 256, 256>>>();

    // 4: fused 3-view GEMM
    dim3 ggrid((TN + 63) / 64, 3);
    k_gemm<<<ggrid, 256>>>(x, W1a, W1b, W1c);

    // 5-6: conv1
    k_init_out1<<<(int)((3L * TN * NH + 255) / 256), 256>>>(b1a, b1b, b1c);
    long warps = 3L * TE;
    k_conv1_scatter<<<(int)((warps * 32 + 255) / 256), 256>>>(ei0, ei1, ei2, ew0, ew1, ew2);

    // 7: relu + feature sum + h@W2
    k_relu_feat_hw<<<(TN + 7) / 8, 256>>>(W2a, W2b, W2c, out);

    // 8-10: conv2 + final
    k_init_o2<<<(3 * TN + 255) / 256, 256>>>(b2a, b2b, b2c);
    k_conv2_scatter<<<(3 * TE + 255) / 256, 256>>>(ei0, ei1, ei2);
    k_final<<<(TN + 255) / 256, 256>>>(out);
}

// round 2
// speedup vs baseline: 2.0192x; 2.0192x over previous
#include <cuda_runtime.h>
#include <cuda_bf16.h>

#define TN 50000
#define TE 800000
#define FIN 256
#define NH 64

typedef unsigned long long ull;

#define FMA2(d,a,b) asm("fma.rn.f32x2 %0,%1,%2,%3;" : "=l"(d) : "l"(a), "l"(b), "l"(d))

// -------- device scratch --------
__device__ float g_XW[TN * 192];        // x @ [W1_v1|W1_v2|W1_v3]
__device__ float g_dinv1[3][TN];
__device__ float g_dinv2[3][TN];
__device__ int   g_cnt[3 * TN];         // per-(branch,dst) in-degree
__device__ int   g_scan[3 * TN];
__device__ int   g_bsum[256];
__device__ int   g_start[3 * TN];
__device__ int   g_cursor[3 * TN];
__device__ int2  g_epack[3 * TE];       // {src, norm-bits} grouped by (branch,dst)
__device__ float g_HV[3][TN];           // (h@W2) * dinv2
__device__ float g_WT[3][64 * 256];     // W1 transposed [view][col][k]

// -------- 1. init --------
__global__ void k_init() {
    int i = blockIdx.x * blockDim.x + threadIdx.x;
    if (i < 3 * TN) {
        ((float*)g_dinv1)[i] = 1.0f;   // self-loop weight
        g_cnt[i] = 0;
    }
}

// -------- 2. degree scatter --------
__global__ void k_deg(const int* ei0, const int* ei1, const int* ei2,
                      const float* ew0, const float* ew1, const float* ew2) {
    int t = blockIdx.x * blockDim.x + threadIdx.x;
    if (t >= 3 * TE) return;
    int b = t / TE;
    int e = t - b * TE;
    const int* ei = (b == 0) ? ei0 : (b == 1) ? ei1 : ei2;
    const float* ew = (b == 0) ? ew0 : (b == 1) ? ew1 : ew2;
    int dst = ei[TE + e];
    atomicAdd(&((float*)g_dinv1)[b * TN + dst], ew[e]);
    atomicAdd(&g_cnt[b * TN + dst], 1);
}

// -------- 3. scan (3 kernels) --------
__global__ void k_scan1() {
    __shared__ int sh[1024];
    int t = threadIdx.x;
    int i = blockIdx.x * 1024 + t;
    int v = (i < 3 * TN) ? g_cnt[i] : 0;
    sh[t] = v;
    for (int off = 1; off < 1024; off <<= 1) {
        __syncthreads();
        int a = (t >= off) ? sh[t - off] : 0;
        __syncthreads();
        sh[t] += a;
    }
    __syncthreads();
    if (i < 3 * TN) g_scan[i] = sh[t] - v;
    if (t == 1023) g_bsum[blockIdx.x] = sh[1023];
}

__global__ void k_scan2(int nb) {
    __shared__ int sh[256];
    int t = threadIdx.x;
    int v = (t < nb) ? g_bsum[t] : 0;
    sh[t] = v;
    for (int off = 1; off < 256; off <<= 1) {
        __syncthreads();
        int a = (t >= off) ? sh[t - off] : 0;
        __syncthreads();
        sh[t] += a;
    }
    __syncthreads();
    g_bsum[t] = sh[t] - v;   // exclusive
}

__global__ void k_scan3() {
    int i = blockIdx.x * blockDim.x + threadIdx.x;
    if (i >= 3 * TN) return;
    int s = g_scan[i] + g_bsum[i >> 10];
    g_start[i] = s;
    g_cursor[i] = s;
}

// -------- 4. deg -> rsqrt --------
__global__ void k_rsqrt() {
    int i = blockIdx.x * blockDim.x + threadIdx.x;
    if (i < 3 * TN) {
        ((float*)g_dinv1)[i] = rsqrtf(((float*)g_dinv1)[i]);
        ((float*)g_dinv2)[i] = rsqrtf((float)g_cnt[i] + 1.0f);  // indeg + self
    }
}

// -------- 5. transpose W1s --------
__global__ void k_wt(const float* W1a, const float* W1b, const float* W1c) {
    int idx = blockIdx.x * blockDim.x + threadIdx.x;
    if (idx >= 3 * FIN * NH) return;
    int v = idx / (FIN * NH);
    int rem = idx - v * FIN * NH;
    int k = rem / NH;
    int c = rem - k * NH;
    const float* W = (v == 0) ? W1a : (v == 1) ? W1b : W1c;
    g_WT[v][c * FIN + k] = W[k * NH + c];
}

// -------- 6. GEMM: 128x64 tile, 8x4/thread, f32x2 K-pair accumulators --------
__global__ void __launch_bounds__(256, 2) k_gemm(const float* __restrict__ x) {
    __shared__ float sx[128][36];
    __shared__ float sw[64][36];
    int v = blockIdx.y;
    int t = threadIdx.x;
    int tx = t & 15;          // col group: cols tx + 16*cc
    int ty = t >> 4;          // row group: rows ty*8 .. +7
    int row0 = blockIdx.x * 128;

    ull acc[8][4];
#pragma unroll
    for (int r = 0; r < 8; r++)
#pragma unroll
        for (int c = 0; c < 4; c++) acc[r][c] = 0ull;

    const float4* x4 = (const float4*)x;
    for (int k0 = 0; k0 < FIN; k0 += 32) {
#pragma unroll
        for (int l = 0; l < 4; l++) {
            int id = t + l * 256;           // 0..1023 : 128 rows x 8 float4
            int r = id >> 3, q = id & 7;
            int gr = row0 + r;
            float4 val = (gr < TN) ? x4[gr * 64 + (k0 >> 2) + q]
                                   : make_float4(0.f, 0.f, 0.f, 0.f);
            *(float4*)&sx[r][q * 4] = val;
        }
#pragma unroll
        for (int l = 0; l < 2; l++) {
            int id = t + l * 256;           // 0..511 : 64 cols x 8 float4
            int c = id >> 3, q = id & 7;
            float4 val = *(const float4*)&g_WT[v][c * FIN + k0 + q * 4];
            *(float4*)&sw[c][q * 4] = val;
        }
        __syncthreads();
#pragma unroll
        for (int kk = 0; kk < 32; kk += 4) {
            ulonglong2 xr[8], wv[4];
#pragma unroll
            for (int rr = 0; rr < 8; rr++)
                xr[rr] = *(const ulonglong2*)&sx[ty * 8 + rr][kk];
#pragma unroll
            for (int cc = 0; cc < 4; cc++)
                wv[cc] = *(const ulonglong2*)&sw[tx + 16 * cc][kk];
#pragma unroll
            for (int rr = 0; rr < 8; rr++)
#pragma unroll
                for (int cc = 0; cc < 4; cc++) {
                    FMA2(acc[rr][cc], xr[rr].x, wv[cc].x);
                    FMA2(acc[rr][cc], xr[rr].y, wv[cc].y);
                }
        }
        __syncthreads();
    }
#pragma unroll
    for (int rr = 0; rr < 8; rr++) {
        int gr = row0 + ty * 8 + rr;
        if (gr < TN) {
#pragma unroll
            for (int cc = 0; cc < 4; cc++) {
                ull a = acc[rr][cc];
                float lo = __int_as_float((int)(a & 0xffffffffu));
                float hi = __int_as_float((int)(a >> 32));
                g_XW[gr * 192 + v * NH + tx + 16 * cc] = lo + hi;
            }
        }
    }
}

// -------- 7. CSR scatter: edge -> bucket --------
__global__ void k_scatter(const int* ei0, const int* ei1, const int* ei2,
                          const float* ew0, const float* ew1, const float* ew2) {
    int t = blockIdx.x * blockDim.x + threadIdx.x;
    if (t >= 3 * TE) return;
    int b = t / TE;
    int e = t - b * TE;
    const int* ei = (b == 0) ? ei0 : (b == 1) ? ei1 : ei2;
    const float* ew = (b == 0) ? ew0 : (b == 1) ? ew1 : ew2;
    int src = ei[e];
    int dst = ei[TE + e];
    float norm = g_dinv1[b][src] * ew[e] * g_dinv1[b][dst];
    int pos = atomicAdd(&g_cursor[b * TN + dst], 1);
    g_epack[pos] = make_int2(src, __float_as_int(norm));
}

// -------- 8. fused conv1 gather + bias + relu + feature-sum + h@W2 --------
__global__ void k_gather(const float* b1a, const float* b1b, const float* b1c,
                         const float* W2a, const float* W2b, const float* W2c,
                         float* __restrict__ out) {
    int warp = (blockIdx.x * blockDim.x + threadIdx.x) >> 5;
    int lane = threadIdx.x & 31;
    if (warp >= TN) return;
    int i = warp;
    float f0 = 0.f, f1 = 0.f;
#pragma unroll
    for (int b = 0; b < 3; b++) {
        const float* b1 = (b == 0) ? b1a : (b == 1) ? b1b : b1c;
        const float* W2 = (b == 0) ? W2a : (b == 1) ? W2b : W2c;
        float d = g_dinv1[b][i];
        const float* xwi = g_XW + i * 192 + b * NH;
        float a0 = b1[lane] + xwi[lane] * d * d;
        float a1 = b1[lane + 32] + xwi[lane + 32] * d * d;
        int s = g_start[b * TN + i];
        int c = g_cnt[b * TN + i];
        if (c > 0) {
            int2 p = g_epack[s];
            for (int j = 0; j < c; j++) {
                int2 np = (j + 1 < c) ? g_epack[s + j + 1] : p;
                float nm = __int_as_float(p.y);
                const float* xs = g_XW + p.x * 192 + b * NH;
                a0 = fmaf(xs[lane], nm, a0);
                a1 = fmaf(xs[lane + 32], nm, a1);
                p = np;
            }
        }
        float h0 = fmaxf(a0, 0.f);
        float h1 = fmaxf(a1, 0.f);
        f0 += h0;
        f1 += h1;
        float dot = h0 * W2[lane] + h1 * W2[lane + 32];
#pragma unroll
        for (int o = 16; o; o >>= 1) dot += __shfl_xor_sync(0xFFFFFFFFu, dot, o);
        if (lane == 0) g_HV[b][i] = dot * g_dinv2[b][i];
    }
    out[TN + i * NH + lane] = f0;
    out[TN + i * NH + lane + 32] = f1;
}

// -------- 9. conv2 gather + final sum --------
__global__ void k_conv2(const float* b2a, const float* b2b, const float* b2c,
                        float* __restrict__ out) {
    int i = blockIdx.x * blockDim.x + threadIdx.x;
    if (i >= TN) return;
    float r = 0.f;
#pragma unroll
    for (int b = 0; b < 3; b++) {
        const float* b2 = (b == 0) ? b2a : (b == 1) ? b2b : b2c;
        int s = g_start[b * TN + i];
        int c = g_cnt[b * TN + i];
        float acc = g_HV[b][i];          // self term (pre-divided by dinv2[i] below)
        for (int j = 0; j < c; j++)
            acc += g_HV[b][g_epack[s + j].x];
        r += b2[0] + g_dinv2[b][i] * acc;
    }
    out[i] = r;
}

extern "C" void kernel_launch(void* const* d_in, const int* in_sizes, int n_in,
                              void* d_out, int out_size) {
    const float* x   = (const float*)d_in[0];
    const int*   ei0 = (const int*)d_in[1];
    const int*   ei1 = (const int*)d_in[2];
    const int*   ei2 = (const int*)d_in[3];
    const float* ew0 = (const float*)d_in[4];
    const float* ew1 = (const float*)d_in[5];
    const float* ew2 = (const float*)d_in[6];
    const float* W1a = (const float*)d_in[7];
    const float* b1a = (const float*)d_in[8];
    const float* W2a = (const float*)d_in[9];
    const float* b2a = (const float*)d_in[10];
    const float* W1b = (const float*)d_in[11];
    const float* b1b = (const float*)d_in[12];
    const float* W2b = (const float*)d_in[13];
    const float* b2b = (const float*)d_in[14];
    const float* W1c = (const float*)d_in[15];
    const float* b1c = (const float*)d_in[16];
    const float* W2c = (const float*)d_in[17];
    const float* b2c = (const float*)d_in[18];
    float* out = (float*)d_out;

    int nb = (3 * TN + 1023) / 1024;   // 147 scan blocks

    k_init<<<(3 * TN + 255) / 256, 256>>>();
    k_deg<<<(3 * TE + 255) / 256, 256>>>(ei0, ei1, ei2, ew0, ew1, ew2);
    k_scan1<<<nb, 1024>>>();
    k_scan2<<<1, 256>>>(nb);
    k_scan3<<<(3 * TN + 255) / 256, 256>>>();
    k_rsqrt<<<(3 * TN + 255) / 256, 256>>>();
    k_wt<<<(3 * FIN * NH + 255) / 256, 256>>>(W1a, W1b, W1c);

    dim3 ggrid((TN + 127) / 128, 3);
    k_gemm<<<ggrid, 256>>>(x);

    k_scatter<<<(3 * TE + 255) / 256, 256>>>(ei0, ei1, ei2, ew0, ew1, ew2);
    k_gather<<<(TN * 32 + 255) / 256, 256>>>(b1a, b1b, b1c, W2a, W2b, W2c, out);
    k_conv2<<<(TN + 255) / 256, 256>>>(b2a, b2b, b2c, out);
}

// round 5
// speedup vs baseline: 2.4307x; 1.2038x over previous
#include <cuda_runtime.h>
#include <cuda_bf16.h>
#include <cstdint>

#define TN 50000
#define TE 800000
#define FIN 256
#define NH 64

// ---------------- device scratch ----------------
__device__ float g_XW[TN * 192];          // x @ [W1_v1|W1_v2|W1_v3]
__device__ float g_dinv1[3 * TN];
__device__ float g_dinv2[3 * TN];
__device__ int   g_cnt[3 * TN];
__device__ int   g_scan[3 * TN];
__device__ int   g_bsum[256];
__device__ int   g_start[3 * TN];
__device__ int   g_rank[3 * TE];
__device__ int2  g_epack[3 * TE];         // {src, norm-bits} CSR-grouped by (branch,dst)
__device__ float g_HV[3][TN];             // (h@W2) * dinv2
__device__ uint32_t g_WBH[192 * 128];     // bf16x2 kpair-packed W hi, [n=192][kpair=128]
__device__ uint32_t g_WBL[192 * 128];     // lo part

#define MMA16816(d, a, b) \
    asm volatile("mma.sync.aligned.m16n8k16.row.col.f32.bf16.bf16.f32 " \
                 "{%0,%1,%2,%3},{%4,%5,%6,%7},{%8,%9},{%0,%1,%2,%3};" \
                 : "+f"((d)[0]), "+f"((d)[1]), "+f"((d)[2]), "+f"((d)[3]) \
                 : "r"((a)[0]), "r"((a)[1]), "r"((a)[2]), "r"((a)[3]), \
                   "r"((b)[0]), "r"((b)[1]))

__device__ __forceinline__ uint32_t pack_bf16x2(float x, float y) {
    __nv_bfloat16 hx = __float2bfloat16(x);
    __nv_bfloat16 hy = __float2bfloat16(y);
    return (uint32_t)__bfloat16_as_ushort(hx) |
           ((uint32_t)__bfloat16_as_ushort(hy) << 16);
}

// ---------------- 1. init degrees + W bf16-split prep ----------------
__global__ void k_initwb(const float* W1a, const float* W1b, const float* W1c) {
    int i = blockIdx.x * blockDim.x + threadIdx.x;
    if (i < 3 * TN) {
        g_dinv1[i] = 1.0f;   // self-loop weight
        g_cnt[i] = 0;
    }
    if (i < 192 * 128) {
        int np = i >> 7;            // 0..191 concatenated col
        int kp = i & 127;           // kpair
        int v = np >> 6;
        int n = np & 63;
        const float* W = (v == 0) ? W1a : (v == 1) ? W1b : W1c;
        float w0 = W[(2 * kp) * NH + n];
        float w1 = W[(2 * kp + 1) * NH + n];
        __nv_bfloat16 h0 = __float2bfloat16(w0);
        __nv_bfloat16 h1 = __float2bfloat16(w1);
        g_WBH[np * 128 + kp] = (uint32_t)__bfloat16_as_ushort(h0) |
                               ((uint32_t)__bfloat16_as_ushort(h1) << 16);
        g_WBL[np * 128 + kp] = pack_bf16x2(w0 - __bfloat162float(h0),
                                           w1 - __bfloat162float(h1));
    }
}

// ---------------- 2. degree scatter + rank ----------------
__global__ void k_deg(const int* ei0, const int* ei1, const int* ei2,
                      const float* ew0, const float* ew1, const float* ew2) {
    int t = blockIdx.x * blockDim.x + threadIdx.x;
    if (t >= 3 * TE) return;
    int b = t / TE;
    int e = t - b * TE;
    const int* ei = (b == 0) ? ei0 : (b == 1) ? ei1 : ei2;
    const float* ew = (b == 0) ? ew0 : (b == 1) ? ew1 : ew2;
    int dst = ei[TE + e];
    g_rank[t] = atomicAdd(&g_cnt[b * TN + dst], 1);
    atomicAdd(&g_dinv1[b * TN + dst], ew[e]);
}

// ---------------- 3. scan ----------------
__global__ void k_scan1() {
    __shared__ int sh[1024];
    int t = threadIdx.x;
    int i = blockIdx.x * 1024 + t;
    int v = (i < 3 * TN) ? g_cnt[i] : 0;
    sh[t] = v;
    for (int off = 1; off < 1024; off <<= 1) {
        __syncthreads();
        int a = (t >= off) ? sh[t - off] : 0;
        __syncthreads();
        sh[t] += a;
    }
    __syncthreads();
    if (i < 3 * TN) g_scan[i] = sh[t] - v;
    if (t == 1023) g_bsum[blockIdx.x] = sh[1023];
}
__global__ void k_scan2(int nb) {
    __shared__ int sh[256];
    int t = threadIdx.x;
    int v = (t < nb) ? g_bsum[t] : 0;
    sh[t] = v;
    for (int off = 1; off < 256; off <<= 1) {
        __syncthreads();
        int a = (t >= off) ? sh[t - off] : 0;
        __syncthreads();
        sh[t] += a;
    }
    __syncthreads();
    g_bsum[t] = sh[t] - v;
}
__global__ void k_scan3() {   // + rsqrt fused
    int i = blockIdx.x * blockDim.x + threadIdx.x;
    if (i >= 3 * TN) return;
    g_start[i] = g_scan[i] + g_bsum[i >> 10];
    g_dinv2[i] = rsqrtf((float)g_cnt[i] + 1.0f);
    g_dinv1[i] = rsqrtf(g_dinv1[i]);
}

// ---------------- 4. tensor-core GEMM via mma.sync (bf16 hi/lo split) ----------
// CTA tile 64x192, K-chunks of 64, 256 threads = 8 warps (2M x 4N), warp 32x48.
#define GEMM_SMEM 73728
__global__ void __launch_bounds__(256, 2) k_gemm_mma(const float* __restrict__ x) {
    extern __shared__ uint32_t sm[];
    uint32_t* sAh = sm;                  // [64][36] words
    uint32_t* sAl = sm + 64 * 36;
    uint32_t* sBh = sm + 2 * 64 * 36;    // [192][36] words
    uint32_t* sBl = sm + 2 * 64 * 36 + 192 * 36;

    int tid = threadIdx.x;
    int wid = tid >> 5, lane = tid & 31;
    int wm = wid >> 2, wn = wid & 3;
    int row0 = blockIdx.x * 64;
    int lr = lane >> 2;                  // 0..7
    int lk = lane & 3;                   // 0..3

    float d[2][6][4];
#pragma unroll
    for (int a = 0; a < 2; a++)
#pragma unroll
        for (int b = 0; b < 6; b++)
#pragma unroll
            for (int c = 0; c < 4; c++) d[a][b][c] = 0.f;

    const float2* x2 = (const float2*)x;
    for (int c = 0; c < 4; c++) {
        // A: 64 rows x 32 kpairs, fp32 -> bf16 hi/lo
#pragma unroll
        for (int it = 0; it < 8; it++) {
            int idx = tid + it * 256;
            int r = idx >> 5, kp = idx & 31;
            int gr = row0 + r;
            float2 v = (gr < TN) ? x2[gr * 128 + c * 32 + kp] : make_float2(0.f, 0.f);
            __nv_bfloat16 h0 = __float2bfloat16(v.x);
            __nv_bfloat16 h1 = __float2bfloat16(v.y);
            sAh[r * 36 + kp] = (uint32_t)__bfloat16_as_ushort(h0) |
                               ((uint32_t)__bfloat16_as_ushort(h1) << 16);
            sAl[r * 36 + kp] = pack_bf16x2(v.x - __bfloat162float(h0),
                                           v.y - __bfloat162float(h1));
        }
        // B: 192 cols x 32 kpairs from prepacked words
#pragma unroll
        for (int it = 0; it < 24; it++) {
            int idx = tid + it * 256;
            int n = idx >> 5, kp = idx & 31;
            sBh[n * 36 + kp] = g_WBH[n * 128 + c * 32 + kp];
            sBl[n * 36 + kp] = g_WBL[n * 128 + c * 32 + kp];
        }
        __syncthreads();
#pragma unroll
        for (int ks = 0; ks < 4; ks++) {
            int kw = ks * 8 + lk;
            uint32_t ah[2][4], al[2][4], bh[6][2], bl[6][2];
#pragma unroll
            for (int f = 0; f < 2; f++) {
                int r = wm * 32 + f * 16 + lr;
                ah[f][0] = sAh[r * 36 + kw];
                ah[f][1] = sAh[(r + 8) * 36 + kw];
                ah[f][2] = sAh[r * 36 + kw + 4];
                ah[f][3] = sAh[(r + 8) * 36 + kw + 4];
                al[f][0] = sAl[r * 36 + kw];
                al[f][1] = sAl[(r + 8) * 36 + kw];
                al[f][2] = sAl[r * 36 + kw + 4];
                al[f][3] = sAl[(r + 8) * 36 + kw + 4];
            }
#pragma unroll
            for (int f = 0; f < 6; f++) {
                int n = wn * 48 + f * 8 + lr;
                bh[f][0] = sBh[n * 36 + kw];
                bh[f][1] = sBh[n * 36 + kw + 4];
                bl[f][0] = sBl[n * 36 + kw];
                bl[f][1] = sBl[n * 36 + kw + 4];
            }
#pragma unroll
            for (int fm = 0; fm < 2; fm++)
#pragma unroll
                for (int fn = 0; fn < 6; fn++) {
                    MMA16816(d[fm][fn], ah[fm], bh[fn]);
                    MMA16816(d[fm][fn], al[fm], bh[fn]);
                    MMA16816(d[fm][fn], ah[fm], bl[fn]);
                }
        }
        __syncthreads();
    }
    // epilogue: frag regs -> g_XW
#pragma unroll
    for (int fm = 0; fm < 2; fm++) {
        int gr = row0 + wm * 32 + fm * 16 + lr;
#pragma unroll
        for (int fn = 0; fn < 6; fn++) {
            int col = wn * 48 + fn * 8 + lk * 2;
            if (gr < TN)
                *(float2*)&g_XW[gr * 192 + col] =
                    make_float2(d[fm][fn][0], d[fm][fn][1]);
            if (gr + 8 < TN)
                *(float2*)&g_XW[(gr + 8) * 192 + col] =
                    make_float2(d[fm][fn][2], d[fm][fn][3]);
        }
    }
}

// ---------------- 5. CSR scatter (atomic-free) ----------------
__global__ void k_scatter(const int* ei0, const int* ei1, const int* ei2,
                          const float* ew0, const float* ew1, const float* ew2) {
    int t = blockIdx.x * blockDim.x + threadIdx.x;
    if (t >= 3 * TE) return;
    int b = t / TE;
    int e = t - b * TE;
    const int* ei = (b == 0) ? ei0 : (b == 1) ? ei1 : ei2;
    const float* ew = (b == 0) ? ew0 : (b == 1) ? ew1 : ew2;
    int src = ei[e];
    int dst = ei[TE + e];
    float norm = g_dinv1[b * TN + src] * ew[e] * g_dinv1[b * TN + dst];
    int pos = g_start[b * TN + dst] + g_rank[t];
    g_epack[pos] = make_int2(src, __float_as_int(norm));
}

// ---------------- 6. fused conv1 gather + relu + feat + h@W2 ----------------
__global__ void k_gather(const float* b1a, const float* b1b, const float* b1c,
                         const float* W2a, const float* W2b, const float* W2c,
                         float* __restrict__ out) {
    int warp = (blockIdx.x * blockDim.x + threadIdx.x) >> 5;
    int lane = threadIdx.x & 31;
    if (warp >= TN) return;
    int i = warp;
    float f0 = 0.f, f1 = 0.f;
#pragma unroll
    for (int b = 0; b < 3; b++) {
        const float* b1 = (b == 0) ? b1a : (b == 1) ? b1b : b1c;
        const float* W2 = (b == 0) ? W2a : (b == 1) ? W2b : W2c;
        float dgi = g_dinv1[b * TN + i];
        float2 xwi = ((const float2*)(g_XW + i * 192 + b * 64))[lane];
        float2 bb = ((const float2*)b1)[lane];
        float a0 = bb.x + xwi.x * dgi * dgi;
        float a1 = bb.y + xwi.y * dgi * dgi;
        int s = g_start[b * TN + i];
        int c = g_cnt[b * TN + i];
        if (c > 0) {
            int2 p = g_epack[s];
            for (int j = 0; j < c; j++) {
                int2 np = (j + 1 < c) ? g_epack[s + j + 1] : p;
                float nm = __int_as_float(p.y);
                float2 m = ((const float2*)(g_XW + p.x * 192 + b * 64))[lane];
                a0 = fmaf(m.x, nm, a0);
                a1 = fmaf(m.y, nm, a1);
                p = np;
            }
        }
        float h0 = fmaxf(a0, 0.f);
        float h1 = fmaxf(a1, 0.f);
        f0 += h0;
        f1 += h1;
        float2 w2 = ((const float2*)W2)[lane];
        float dot = h0 * w2.x + h1 * w2.y;
#pragma unroll
        for (int o = 16; o; o >>= 1) dot += __shfl_xor_sync(0xFFFFFFFFu, dot, o);
        if (lane == 0) g_HV[b][i] = dot * g_dinv2[b * TN + i];
    }
    ((float2*)(out + TN + (long)i * NH))[lane] = make_float2(f0, f1);
}

// ---------------- 7. conv2 gather (warp per node) + final sum ----------------
__global__ void k_conv2(const float* b2a, const float* b2b, const float* b2c,
                        float* __restrict__ out) {
    int warp = (blockIdx.x * blockDim.x + threadIdx.x) >> 5;
    int lane = threadIdx.x & 31;
    if (warp >= TN) return;
    int i = warp;
    float r = 0.f;
#pragma unroll
    for (int b = 0; b < 3; b++) {
        const float* b2 = (b == 0) ? b2a : (b == 1) ? b2b : b2c;
        int s = g_start[b * TN + i];
        int c = g_cnt[b * TN + i];
        float acc = 0.f;
        for (int j = lane; j < c; j += 32)
            acc += g_HV[b][g_epack[s + j].x];
#pragma unroll
        for (int o = 16; o; o >>= 1) acc += __shfl_xor_sync(0xFFFFFFFFu, acc, o);
        r += b2[0] + g_dinv2[b * TN + i] * (g_HV[b][i] + acc);
    }
    if (lane == 0) out[i] = r;
}

extern "C" void kernel_launch(void* const* d_in, const int* in_sizes, int n_in,
                              void* d_out, int out_size) {
    const float* x   = (const float*)d_in[0];
    const int*   ei0 = (const int*)d_in[1];
    const int*   ei1 = (const int*)d_in[2];
    const int*   ei2 = (const int*)d_in[3];
    const float* ew0 = (const float*)d_in[4];
    const float* ew1 = (const float*)d_in[5];
    const float* ew2 = (const float*)d_in[6];
    const float* W1a = (const float*)d_in[7];
    const float* b1a = (const float*)d_in[8];
    const float* W2a = (const float*)d_in[9];
    const float* b2a = (const float*)d_in[10];
    const float* W1b = (const float*)d_in[11];
    const float* b1b = (const float*)d_in[12];
    const float* W2b = (const float*)d_in[13];
    const float* b2b = (const float*)d_in[14];
    const float* W1c = (const float*)d_in[15];
    const float* b1c = (const float*)d_in[16];
    const float* W2c = (const float*)d_in[17];
    const float* b2c = (const float*)d_in[18];
    float* out = (float*)d_out;

    cudaFuncSetAttribute(k_gemm_mma, cudaFuncAttributeMaxDynamicSharedMemorySize,
                         GEMM_SMEM);

    int nb = (3 * TN + 1023) / 1024;   // 147

    k_initwb<<<(3 * TN + 255) / 256, 256>>>(W1a, W1b, W1c);
    k_deg<<<(3 * TE + 255) / 256, 256>>>(ei0, ei1, ei2, ew0, ew1, ew2);
    k_scan1<<<nb, 1024>>>();
    k_scan2<<<1, 256>>>(nb);
    k_scan3<<<(3 * TN + 255) / 256, 256>>>();
    k_gemm_mma<<<(TN + 63) / 64, 256, GEMM_SMEM>>>(x);
    k_scatter<<<(3 * TE + 255) / 256, 256>>>(ei0, ei1, ei2, ew0, ew1, ew2);
    k_gather<<<(TN * 32 + 255) / 256, 256>>>(b1a, b1b, b1c, W2a, W2b, W2c, out);
    k_conv2<<<(TN * 32 + 255) / 256, 256>>>(b2a, b2b, b2c, out);
}

// round 6
// speedup vs baseline: 2.8110x; 1.1565x over previous
#include <cuda_runtime.h>
#include <cuda_bf16.h>
#include <cuda_fp16.h>
#include <cstdint>

#define TN 50000
#define TE 800000
#define FIN 256
#define NH 64

// ---------------- device scratch ----------------
__device__ float g_XW[TN * 192];          // fp32 x@W rows (self terms)
__device__ __half2 g_XWH[TN * 96];        // fp16 copy for neighbor messages
__device__ float g_dinv1[3 * TN];
__device__ float g_dinv2[3 * TN];
__device__ int   g_cnt[3 * TN];
__device__ int   g_scan[3 * TN];
__device__ int   g_bsum[256];
__device__ int   g_start[3 * TN];
__device__ int   g_rank[3 * TE];
__device__ int2  g_epack[3 * TE];         // {src, norm-bits} CSR-grouped by (branch,dst)
__device__ float g_HV[3][TN];             // (h@W2) * dinv2
__device__ uint32_t g_WBH[192 * 128];     // bf16x2 kpair-packed W hi
__device__ uint32_t g_WBL[192 * 128];     // lo part

#define MMA16816(d, a, b) \
    asm volatile("mma.sync.aligned.m16n8k16.row.col.f32.bf16.bf16.f32 " \
                 "{%0,%1,%2,%3},{%4,%5,%6,%7},{%8,%9},{%0,%1,%2,%3};" \
                 : "+f"((d)[0]), "+f"((d)[1]), "+f"((d)[2]), "+f"((d)[3]) \
                 : "r"((a)[0]), "r"((a)[1]), "r"((a)[2]), "r"((a)[3]), \
                   "r"((b)[0]), "r"((b)[1]))

__device__ __forceinline__ uint32_t pack_bf16x2(float x, float y) {
    __nv_bfloat16 hx = __float2bfloat16(x);
    __nv_bfloat16 hy = __float2bfloat16(y);
    return (uint32_t)__bfloat16_as_ushort(hx) |
           ((uint32_t)__bfloat16_as_ushort(hy) << 16);
}

// ---------------- 1. init degrees + W bf16-split prep ----------------
__global__ void k_initwb(const float* W1a, const float* W1b, const float* W1c) {
    int i = blockIdx.x * blockDim.x + threadIdx.x;
    if (i < 3 * TN) {
        g_dinv1[i] = 1.0f;   // self-loop weight
        g_cnt[i] = 0;
    }
    if (i < 192 * 128) {
        int np = i >> 7;
        int kp = i & 127;
        int v = np >> 6;
        int n = np & 63;
        const float* W = (v == 0) ? W1a : (v == 1) ? W1b : W1c;
        float w0 = W[(2 * kp) * NH + n];
        float w1 = W[(2 * kp + 1) * NH + n];
        __nv_bfloat16 h0 = __float2bfloat16(w0);
        __nv_bfloat16 h1 = __float2bfloat16(w1);
        g_WBH[np * 128 + kp] = (uint32_t)__bfloat16_as_ushort(h0) |
                               ((uint32_t)__bfloat16_as_ushort(h1) << 16);
        g_WBL[np * 128 + kp] = pack_bf16x2(w0 - __bfloat162float(h0),
                                           w1 - __bfloat162float(h1));
    }
}

// ---------------- 2. degree scatter + rank ----------------
__global__ void k_deg(const int* ei0, const int* ei1, const int* ei2,
                      const float* ew0, const float* ew1, const float* ew2) {
    int t = blockIdx.x * blockDim.x + threadIdx.x;
    if (t >= 3 * TE) return;
    int b = t / TE;
    int e = t - b * TE;
    const int* ei = (b == 0) ? ei0 : (b == 1) ? ei1 : ei2;
    const float* ew = (b == 0) ? ew0 : (b == 1) ? ew1 : ew2;
    int dst = ei[TE + e];
    g_rank[t] = atomicAdd(&g_cnt[b * TN + dst], 1);
    atomicAdd(&g_dinv1[b * TN + dst], ew[e]);
}

// ---------------- 3. scan ----------------
__global__ void k_scan1() {
    __shared__ int sh[1024];
    int t = threadIdx.x;
    int i = blockIdx.x * 1024 + t;
    int v = (i < 3 * TN) ? g_cnt[i] : 0;
    sh[t] = v;
    for (int off = 1; off < 1024; off <<= 1) {
        __syncthreads();
        int a = (t >= off) ? sh[t - off] : 0;
        __syncthreads();
        sh[t] += a;
    }
    __syncthreads();
    if (i < 3 * TN) g_scan[i] = sh[t] - v;
    if (t == 1023) g_bsum[blockIdx.x] = sh[1023];
}
__global__ void k_scan2(int nb) {
    __shared__ int sh[256];
    int t = threadIdx.x;
    int v = (t < nb) ? g_bsum[t] : 0;
    sh[t] = v;
    for (int off = 1; off < 256; off <<= 1) {
        __syncthreads();
        int a = (t >= off) ? sh[t - off] : 0;
        __syncthreads();
        sh[t] += a;
    }
    __syncthreads();
    g_bsum[t] = sh[t] - v;
}
__global__ void k_scan3() {   // + rsqrt fused
    int i = blockIdx.x * blockDim.x + threadIdx.x;
    if (i >= 3 * TN) return;
    g_start[i] = g_scan[i] + g_bsum[i >> 10];
    g_dinv2[i] = rsqrtf((float)g_cnt[i] + 1.0f);
    g_dinv1[i] = rsqrtf(g_dinv1[i]);
}

// ---------------- 4. tensor-core GEMM via mma.sync (bf16 hi/lo split) ----------
#define GEMM_SMEM 73728
__global__ void __launch_bounds__(256, 2) k_gemm_mma(const float* __restrict__ x) {
    extern __shared__ uint32_t sm[];
    uint32_t* sAh = sm;                  // [64][36]
    uint32_t* sAl = sm + 64 * 36;
    uint32_t* sBh = sm + 2 * 64 * 36;    // [192][36]
    uint32_t* sBl = sm + 2 * 64 * 36 + 192 * 36;

    int tid = threadIdx.x;
    int wid = tid >> 5, lane = tid & 31;
    int wm = wid >> 2, wn = wid & 3;
    int row0 = blockIdx.x * 64;
    int lr = lane >> 2;
    int lk = lane & 3;

    float d[2][6][4];
#pragma unroll
    for (int a = 0; a < 2; a++)
#pragma unroll
        for (int b = 0; b < 6; b++)
#pragma unroll
            for (int c = 0; c < 4; c++) d[a][b][c] = 0.f;

    const float2* x2 = (const float2*)x;
    for (int c = 0; c < 4; c++) {
#pragma unroll
        for (int it = 0; it < 8; it++) {
            int idx = tid + it * 256;
            int r = idx >> 5, kp = idx & 31;
            int gr = row0 + r;
            float2 v = (gr < TN) ? x2[gr * 128 + c * 32 + kp] : make_float2(0.f, 0.f);
            __nv_bfloat16 h0 = __float2bfloat16(v.x);
            __nv_bfloat16 h1 = __float2bfloat16(v.y);
            sAh[r * 36 + kp] = (uint32_t)__bfloat16_as_ushort(h0) |
                               ((uint32_t)__bfloat16_as_ushort(h1) << 16);
            sAl[r * 36 + kp] = pack_bf16x2(v.x - __bfloat162float(h0),
                                           v.y - __bfloat162float(h1));
        }
#pragma unroll
        for (int it = 0; it < 24; it++) {
            int idx = tid + it * 256;
            int n = idx >> 5, kp = idx & 31;
            sBh[n * 36 + kp] = g_WBH[n * 128 + c * 32 + kp];
            sBl[n * 36 + kp] = g_WBL[n * 128 + c * 32 + kp];
        }
        __syncthreads();
#pragma unroll
        for (int ks = 0; ks < 4; ks++) {
            int kw = ks * 8 + lk;
            uint32_t ah[2][4], al[2][4], bh[6][2], bl[6][2];
#pragma unroll
            for (int f = 0; f < 2; f++) {
                int r = wm * 32 + f * 16 + lr;
                ah[f][0] = sAh[r * 36 + kw];
                ah[f][1] = sAh[(r + 8) * 36 + kw];
                ah[f][2] = sAh[r * 36 + kw + 4];
                ah[f][3] = sAh[(r + 8) * 36 + kw + 4];
                al[f][0] = sAl[r * 36 + kw];
                al[f][1] = sAl[(r + 8) * 36 + kw];
                al[f][2] = sAl[r * 36 + kw + 4];
                al[f][3] = sAl[(r + 8) * 36 + kw + 4];
            }
#pragma unroll
            for (int f = 0; f < 6; f++) {
                int n = wn * 48 + f * 8 + lr;
                bh[f][0] = sBh[n * 36 + kw];
                bh[f][1] = sBh[n * 36 + kw + 4];
                bl[f][0] = sBl[n * 36 + kw];
                bl[f][1] = sBl[n * 36 + kw + 4];
            }
#pragma unroll
            for (int fm = 0; fm < 2; fm++)
#pragma unroll
                for (int fn = 0; fn < 6; fn++) {
                    MMA16816(d[fm][fn], ah[fm], bh[fn]);
                    MMA16816(d[fm][fn], al[fm], bh[fn]);
                    MMA16816(d[fm][fn], ah[fm], bl[fn]);
                }
        }
        __syncthreads();
    }
#pragma unroll
    for (int fm = 0; fm < 2; fm++) {
        int gr = row0 + wm * 32 + fm * 16 + lr;
#pragma unroll
        for (int fn = 0; fn < 6; fn++) {
            int col = wn * 48 + fn * 8 + lk * 2;
            if (gr < TN) {
                *(float2*)&g_XW[gr * 192 + col] = make_float2(d[fm][fn][0], d[fm][fn][1]);
                g_XWH[gr * 96 + (col >> 1)] = __floats2half2_rn(d[fm][fn][0], d[fm][fn][1]);
            }
            if (gr + 8 < TN) {
                *(float2*)&g_XW[(gr + 8) * 192 + col] = make_float2(d[fm][fn][2], d[fm][fn][3]);
                g_XWH[(gr + 8) * 96 + (col >> 1)] = __floats2half2_rn(d[fm][fn][2], d[fm][fn][3]);
            }
        }
    }
}

// ---------------- 5. CSR scatter (atomic-free) ----------------
__global__ void k_scatter(const int* ei0, const int* ei1, const int* ei2,
                          const float* ew0, const float* ew1, const float* ew2) {
    int t = blockIdx.x * blockDim.x + threadIdx.x;
    if (t >= 3 * TE) return;
    int b = t / TE;
    int e = t - b * TE;
    const int* ei = (b == 0) ? ei0 : (b == 1) ? ei1 : ei2;
    const float* ew = (b == 0) ? ew0 : (b == 1) ? ew1 : ew2;
    int src = ei[e];
    int dst = ei[TE + e];
    float norm = g_dinv1[b * TN + src] * ew[e] * g_dinv1[b * TN + dst];
    int pos = g_start[b * TN + dst] + g_rank[t];
    g_epack[pos] = make_int2(src, __float_as_int(norm));
}

// ---------------- 6. fused conv1 gather (fp16 messages, MLP-4) ----------------
__global__ void k_gather(const float* b1a, const float* b1b, const float* b1c,
                         const float* W2a, const float* W2b, const float* W2c,
                         float* __restrict__ out) {
    int warp = (blockIdx.x * blockDim.x + threadIdx.x) >> 5;
    int lane = threadIdx.x & 31;
    if (warp >= TN) return;
    int i = warp;
    float f0 = 0.f, f1 = 0.f;
#pragma unroll
    for (int b = 0; b < 3; b++) {
        const float* b1 = (b == 0) ? b1a : (b == 1) ? b1b : b1c;
        const float* W2 = (b == 0) ? W2a : (b == 1) ? W2b : W2c;
        float dgi = g_dinv1[b * TN + i];
        float2 xwi = ((const float2*)(g_XW + i * 192 + b * 64))[lane];
        float2 bb = ((const float2*)b1)[lane];
        float a0 = bb.x + xwi.x * dgi * dgi;
        float a1 = bb.y + xwi.y * dgi * dgi;
        int s = g_start[b * TN + i];
        int c = g_cnt[b * TN + i];
        int boff = b * 32 + lane;
        int j = 0;
#pragma unroll 1
        for (; j + 4 <= c; j += 4) {
            int2 p0 = g_epack[s + j];
            int2 p1 = g_epack[s + j + 1];
            int2 p2 = g_epack[s + j + 2];
            int2 p3 = g_epack[s + j + 3];
            float2 m0 = __half22float2(g_XWH[p0.x * 96 + boff]);
            float2 m1 = __half22float2(g_XWH[p1.x * 96 + boff]);
            float2 m2 = __half22float2(g_XWH[p2.x * 96 + boff]);
            float2 m3 = __half22float2(g_XWH[p3.x * 96 + boff]);
            float n0 = __int_as_float(p0.y), n1 = __int_as_float(p1.y);
            float n2 = __int_as_float(p2.y), n3 = __int_as_float(p3.y);
            a0 = fmaf(m0.x, n0, a0); a1 = fmaf(m0.y, n0, a1);
            a0 = fmaf(m1.x, n1, a0); a1 = fmaf(m1.y, n1, a1);
            a0 = fmaf(m2.x, n2, a0); a1 = fmaf(m2.y, n2, a1);
            a0 = fmaf(m3.x, n3, a0); a1 = fmaf(m3.y, n3, a1);
        }
#pragma unroll 1
        for (; j < c; j++) {
            int2 p = g_epack[s + j];
            float nm = __int_as_float(p.y);
            float2 m = __half22float2(g_XWH[p.x * 96 + boff]);
            a0 = fmaf(m.x, nm, a0);
            a1 = fmaf(m.y, nm, a1);
        }
        float h0 = fmaxf(a0, 0.f);
        float h1 = fmaxf(a1, 0.f);
        f0 += h0;
        f1 += h1;
        float2 w2 = ((const float2*)W2)[lane];
        float dot = h0 * w2.x + h1 * w2.y;
#pragma unroll
        for (int o = 16; o; o >>= 1) dot += __shfl_xor_sync(0xFFFFFFFFu, dot, o);
        if (lane == 0) g_HV[b][i] = dot * g_dinv2[b * TN + i];
    }
    ((float2*)(out + TN + (long)i * NH))[lane] = make_float2(f0, f1);
}

// ---------------- 7. conv2 gather (warp per node) + final sum ----------------
__global__ void k_conv2(const float* b2a, const float* b2b, const float* b2c,
                        float* __restrict__ out) {
    int warp = (blockIdx.x * blockDim.x + threadIdx.x) >> 5;
    int lane = threadIdx.x & 31;
    if (warp >= TN) return;
    int i = warp;
    float r = 0.f;
#pragma unroll
    for (int b = 0; b < 3; b++) {
        const float* b2 = (b == 0) ? b2a : (b == 1) ? b2b : b2c;
        int s = g_start[b * TN + i];
        int c = g_cnt[b * TN + i];
        float acc = 0.f;
        for (int j = lane; j < c; j += 32)
            acc += g_HV[b][g_epack[s + j].x];
#pragma unroll
        for (int o = 16; o; o >>= 1) acc += __shfl_xor_sync(0xFFFFFFFFu, acc, o);
        r += b2[0] + g_dinv2[b * TN + i] * (g_HV[b][i] + acc);
    }
    if (lane == 0) out[i] = r;
}

extern "C" void kernel_launch(void* const* d_in, const int* in_sizes, int n_in,
                              void* d_out, int out_size) {
    const float* x   = (const float*)d_in[0];
    const int*   ei0 = (const int*)d_in[1];
    const int*   ei1 = (const int*)d_in[2];
    const int*   ei2 = (const int*)d_in[3];
    const float* ew0 = (const float*)d_in[4];
    const float* ew1 = (const float*)d_in[5];
    const float* ew2 = (const float*)d_in[6];
    const float* W1a = (const float*)d_in[7];
    const float* b1a = (const float*)d_in[8];
    const float* W2a = (const float*)d_in[9];
    const float* b2a = (const float*)d_in[10];
    const float* W1b = (const float*)d_in[11];
    const float* b1b = (const float*)d_in[12];
    const float* W2b = (const float*)d_in[13];
    const float* b2b = (const float*)d_in[14];
    const float* W1c = (const float*)d_in[15];
    const float* b1c = (const float*)d_in[16];
    const float* W2c = (const float*)d_in[17];
    const float* b2c = (const float*)d_in[18];
    float* out = (float*)d_out;

    static cudaStream_t s1 = nullptr;
    static cudaEvent_t evFork = nullptr, evJoin = nullptr;
    if (!s1) {
        cudaStreamCreateWithFlags(&s1, cudaStreamNonBlocking);
        cudaEventCreateWithFlags(&evFork, cudaEventDisableTiming);
        cudaEventCreateWithFlags(&evJoin, cudaEventDisableTiming);
        cudaFuncSetAttribute(k_gemm_mma, cudaFuncAttributeMaxDynamicSharedMemorySize,
                             GEMM_SMEM);
    }

    int nb = (3 * TN + 1023) / 1024;

    // common prep
    k_initwb<<<(3 * TN + 255) / 256, 256>>>(W1a, W1b, W1c);

    // fork: GEMM on side stream, edge pipeline on main stream
    cudaEventRecord(evFork, 0);
    cudaStreamWaitEvent(s1, evFork, 0);
    k_gemm_mma<<<(TN + 63) / 64, 256, GEMM_SMEM, s1>>>(x);
    cudaEventRecord(evJoin, s1);

    k_deg<<<(3 * TE + 255) / 256, 256>>>(ei0, ei1, ei2, ew0, ew1, ew2);
    k_scan1<<<nb, 1024>>>();
    k_scan2<<<1, 256>>>(nb);
    k_scan3<<<(3 * TN + 255) / 256, 256>>>();
    k_scatter<<<(3 * TE + 255) / 256, 256>>>(ei0, ei1, ei2, ew0, ew1, ew2);

    // join before gather (needs XW/XWH)
    cudaStreamWaitEvent(0, evJoin, 0);
    k_gather<<<(TN * 32 + 255) / 256, 256>>>(b1a, b1b, b1c, W2a, W2b, W2c, out);
    k_conv2<<<(TN * 32 + 255) / 256, 256>>>(b2a, b2b, b2c, out);
}